// round 5
// baseline (speedup 1.0000x reference)
#include <cuda_runtime.h>
#include <float.h>
#include <math.h>

#define MAXT 8192
#define NB   256          // direction bins (one block each in build+query)
#define CAP  128          // max candidates per bin (expect ~5-10)

// Scratch (graph-capturable: no allocs, no cross-launch state; everything
// below is fully overwritten by kernel 1 each launch).
//   g_QQ[i] = { pack(Qprog.x, Qstack.x), pack(Qprog.y, Qstack.y) }
//   g_KK[j] = { pack(Kprog.x, Kstack.x), pack(Kprog.y, Kstack.y) }
//   g_KN[j] = pack(|Kprog_j|, |Kstack_j|)
//   g_binPS[i] = query i's direction bin, prog in low 16, stack in high 16
__device__ ulonglong2 g_QQ[MAXT], g_KK[MAXT];
__device__ unsigned long long g_KN[MAXT];
__device__ unsigned g_binPS[MAXT];
__device__ float g_Vop[MAXT], g_Varg[MAXT], g_Vstk[MAXT];

__device__ __forceinline__ unsigned long long packf2(float lo, float hi) {
    return ((unsigned long long)__float_as_uint(hi) << 32) | (unsigned long long)__float_as_uint(lo);
}
__device__ __forceinline__ float lo32(unsigned long long v) { return __uint_as_float((unsigned)v); }
__device__ __forceinline__ float hi32(unsigned long long v) { return __uint_as_float((unsigned)(v >> 32)); }

// sm_103a packed fp32 pair math (PTX-only; ptxas won't auto-fuse).
__device__ __forceinline__ unsigned long long mul2(unsigned long long a, unsigned long long b) {
    unsigned long long r;
    asm("mul.rn.f32x2 %0, %1, %2;" : "=l"(r) : "l"(a), "l"(b));
    return r;
}
__device__ __forceinline__ unsigned long long fma2(unsigned long long a, unsigned long long b, unsigned long long c) {
    unsigned long long r;
    asm("fma.rn.f32x2 %0, %1, %2, %3;" : "=l"(r) : "l"(a), "l"(b), "l"(c));
    return r;
}

#define PI_F 3.14159265358979f
#define TWO_PI_F 6.2831853071795865f

__device__ __forceinline__ unsigned qbins(float qpx, float qpy, float qsx, float qsy) {
    const float SC = NB / TWO_PI_F;
    int bP = (int)((atan2f(qpy, qpx) + PI_F) * SC);
    bP = min(max(bP, 0), NB - 1);
    int bS = (int)((atan2f(qsy, qsx) + PI_F) * SC);
    bS = min(max(bS, 0), NB - 1);
    return (unsigned)bP | ((unsigned)bS << 16);
}

// ---------------------------------------------------------------------------
// Kernel 1a: projections specialized for D == 36, plus per-query direction
// bins and per-key norms (computed in the store-latency shadow).
// 32 rows/block, 4 threads/row (9 dims), float4 staging, full unroll.
// ---------------------------------------------------------------------------
#define PD  36
#define PR  32
#define PTH 128

__global__ __launch_bounds__(PTH) void proj36_kernel(
        const float* __restrict__ emb,
        const float* __restrict__ wqp, const float* __restrict__ wkp,
        const float* __restrict__ wvop, const float* __restrict__ wvarg,
        const float* __restrict__ wqs, const float* __restrict__ wks,
        const float* __restrict__ wvs, int T) {
    __shared__ float sw[11 * PD];
    __shared__ float se[PR * PD];
    const int tid = threadIdx.x;

    for (int k = tid; k < 2 * PD; k += PTH) {
        sw[k]          = wqp[k];
        sw[2 * PD + k] = wkp[k];
        sw[4 * PD + k] = wqs[k];
        sw[6 * PD + k] = wks[k];
    }
    if (tid < PD) {
        sw[8 * PD + tid]  = wvop[tid];
        sw[9 * PD + tid]  = wvarg[tid];
        sw[10 * PD + tid] = wvs[tid];
    }

    const int base = blockIdx.x * PR;
    const float4* emb4 = (const float4*)(emb + (size_t)base * PD);
#pragma unroll
    for (int v = 0; v < (PR * PD / 4) / PTH + 1; v++) {
        int idx = tid + v * PTH;
        if (idx < PR * PD / 4) ((float4*)se)[idx] = emb4[idx];
    }
    __syncthreads();

    const int row = tid >> 2, part = tid & 3;
    const float* r0 = se + row * PD + part * 9;

    float rv[9];
#pragma unroll
    for (int dd = 0; dd < 9; dd++) rv[dd] = r0[dd];

    // c: 0=Qp.x 1=Qp.y 2=Kp.x 3=Kp.y 4=Qs.x 5=Qs.y 6=Ks.x 7=Ks.y 8=Vop 9=Varg 10=Vstk
    float a[11];
#pragma unroll
    for (int c = 0; c < 11; c++) a[c] = 0.f;
#pragma unroll
    for (int c = 0; c < 11; c++) {
        const float* wc = sw + c * PD + part * 9;
#pragma unroll
        for (int dd = 0; dd < 9; dd++) a[c] = fmaf(rv[dd], wc[dd], a[c]);
    }
#pragma unroll
    for (int c = 0; c < 11; c++) {
        a[c] += __shfl_down_sync(0xffffffffu, a[c], 1);
        a[c] += __shfl_down_sync(0xffffffffu, a[c], 2);
    }
    if (part == 0) {
        int i = base + row;
        g_QQ[i] = make_ulonglong2(packf2(a[0], a[4]), packf2(a[1], a[5]));
        g_KK[i] = make_ulonglong2(packf2(a[2], a[6]), packf2(a[3], a[7]));
        g_KN[i] = packf2(sqrtf(fmaf(a[2], a[2], a[3] * a[3])),
                         sqrtf(fmaf(a[6], a[6], a[7] * a[7])));
        g_binPS[i] = qbins(a[0], a[1], a[4], a[5]);
        g_Vop[i] = a[8]; g_Varg[i] = a[9]; g_Vstk[i] = a[10];
    }
}

// ---------------------------------------------------------------------------
// Kernel 1b: generic-D fallback (not used for the benchmark shape).
// ---------------------------------------------------------------------------
__global__ void proj_generic_kernel(
        const float* __restrict__ emb,
        const float* __restrict__ wqp, const float* __restrict__ wkp,
        const float* __restrict__ wvop, const float* __restrict__ wvarg,
        const float* __restrict__ wqs, const float* __restrict__ wks,
        const float* __restrict__ wvs, int T, int D) {
    extern __shared__ float sw[];
    const int tid = threadIdx.x;
    for (int k = tid; k < 2 * D; k += blockDim.x) {
        sw[k]         = wqp[k];
        sw[2 * D + k] = wkp[k];
        sw[4 * D + k] = wqs[k];
        sw[6 * D + k] = wks[k];
    }
    for (int k = tid; k < D; k += blockDim.x) {
        sw[8 * D + k]  = wvop[k];
        sw[9 * D + k]  = wvarg[k];
        sw[10 * D + k] = wvs[k];
    }
    __syncthreads();
    int i = blockIdx.x * blockDim.x + tid;
    if (i >= T) return;
    const float* e = emb + (size_t)i * D;
    float a[11];
#pragma unroll
    for (int c = 0; c < 11; c++) a[c] = 0.f;
    for (int d = 0; d < D; d++) {
        float ev = e[d];
#pragma unroll
        for (int c = 0; c < 11; c++) a[c] = fmaf(ev, sw[c * D + d], a[c]);
    }
    g_QQ[i] = make_ulonglong2(packf2(a[0], a[4]), packf2(a[1], a[5]));
    g_KK[i] = make_ulonglong2(packf2(a[2], a[6]), packf2(a[3], a[7]));
    g_KN[i] = packf2(sqrtf(fmaf(a[2], a[2], a[3] * a[3])),
                     sqrtf(fmaf(a[6], a[6], a[7] * a[7])));
    g_binPS[i] = qbins(a[0], a[1], a[4], a[5]);
    g_Vop[i] = a[8]; g_Varg[i] = a[9]; g_Vstk[i] = a[10];
}

// ---------------------------------------------------------------------------
// Kernel 2: fused build + query. One block per direction bin.
//  Phase A (threshold): subsample 1 key/thread; ref = s_u(r) - A'|r|; max.
//  Phase B (collect):   single scan; keep keys with s_u(k) + A'|k| >= thresh.
//     Correctness: for the true argmax k* of any query direction inside this
//     bin, s_u(k*) + (D/2)|k*| >= s_u(r) - (D/2)|r| for every r (Lipschitz);
//     A' = 1.25*D/2 inflates both sides conservatively, so k* is collected.
//     The subsample-derived thresh is <= the exact one (superset). At least
//     the subsample max collects itself, so the list is never empty.
//  Phase C (query): scan per-query bins; resolve queries of this bin against
//     the smem candidate list with exact fp32 scores + first-index tie-break
//     (order-independent, matches jnp.argmax).
// ---------------------------------------------------------------------------
#define BTH 256

__global__ __launch_bounds__(BTH) void build_query_kernel(float* __restrict__ out, int T) {
    __shared__ int scandP[CAP], scandS[CAP];
    __shared__ int scnt[2];
    __shared__ float sred[2][BTH / 32];
    __shared__ float sth[2];

    const int b = blockIdx.x;
    const int tid = threadIdx.x, lane = tid & 31, w = tid >> 5;
    const float DLT = TWO_PI_F / NB;
    const float th = -PI_F + (b + 0.5f) * DLT;
    const float ux = cosf(th), uy = sinf(th);
    const unsigned long long ua = packf2(ux, ux), ub = packf2(uy, uy);
    const float Ap = 0.625f * DLT;                      // 1.25 * DLT/2
    const unsigned long long apos = packf2(Ap, Ap);
    const unsigned long long aneg = packf2(-Ap, -Ap);

    // ---- phase A: subsample threshold ----
    {
        int j0 = (int)(((long long)tid * T) / BTH);
        ulonglong2 kk = g_KK[j0];
        unsigned long long kn = g_KN[j0];
        unsigned long long s = fma2(ua, kk.x, mul2(ub, kk.y));
        unsigned long long r = fma2(aneg, kn, s);       // s - A'|k|
        float vP = lo32(r), vS = hi32(r);
#pragma unroll
        for (int off = 16; off; off >>= 1) {
            vP = fmaxf(vP, __shfl_xor_sync(0xffffffffu, vP, off));
            vS = fmaxf(vS, __shfl_xor_sync(0xffffffffu, vS, off));
        }
        if (lane == 0) { sred[0][w] = vP; sred[1][w] = vS; }
    }
    if (tid < 2) scnt[tid] = 0;
    __syncthreads();
    if (tid < 2) {
        float v = sred[tid][0];
#pragma unroll
        for (int k = 1; k < BTH / 32; k++) v = fmaxf(v, sred[tid][k]);
        sth[tid] = v;
    }
    __syncthreads();
    const float tP = sth[0], tS = sth[1];

    // ---- phase B: single-scan candidate collection into smem ----
#pragma unroll 4
    for (int j = tid; j < T; j += BTH) {
        ulonglong2 kk = g_KK[j];
        unsigned long long kn = g_KN[j];
        unsigned long long s = fma2(ua, kk.x, mul2(ub, kk.y));
        unsigned long long t2 = fma2(apos, kn, s);      // s + A'|k|
        if (lo32(t2) >= tP) { int p = atomicAdd(&scnt[0], 1); if (p < CAP) scandP[p] = j; }
        if (hi32(t2) >= tS) { int p = atomicAdd(&scnt[1], 1); if (p < CAP) scandS[p] = j; }
    }
    __syncthreads();
    const int nP = min(scnt[0], CAP), nS = min(scnt[1], CAP);

    // ---- phase C: resolve this bin's queries ----
    for (int j = tid; j < T; j += BTH) {
        const unsigned bp = g_binPS[j];
        const bool doP = ((bp & 0xffffu) == (unsigned)b);
        const bool doS = ((bp >> 16) == (unsigned)b);
        if (doP || doS) {
            ulonglong2 q = g_QQ[j];
            if (doP) {
                const float qx = lo32(q.x), qy = lo32(q.y);
                float best = -FLT_MAX; int bi = 0x7fffffff;
                for (int t = 0; t < nP; t++) {
                    int c = scandP[t];
                    ulonglong2 k2 = g_KK[c];
                    float sc = fmaf(qx, lo32(k2.x), __fmul_rn(qy, lo32(k2.y)));
                    if (sc > best || (sc == best && c < bi)) { best = sc; bi = c; }
                }
                out[j]     = g_Vop[bi];
                out[T + j] = g_Varg[bi];
            }
            if (doS) {
                const float qx = hi32(q.x), qy = hi32(q.y);
                float best = -FLT_MAX; int bi = 0x7fffffff;
                for (int t = 0; t < nS; t++) {
                    int c = scandS[t];
                    ulonglong2 k2 = g_KK[c];
                    float sc = fmaf(qx, hi32(k2.x), __fmul_rn(qy, hi32(k2.y)));
                    if (sc > best || (sc == best && c < bi)) { best = sc; bi = c; }
                }
                out[2 * T + j] = g_Vstk[bi];
            }
        }
    }
}

extern "C" void kernel_launch(void* const* d_in, const int* in_sizes, int n_in,
                              void* d_out, int out_size) {
    const float* emb   = (const float*)d_in[0];
    const float* wqp   = (const float*)d_in[1];
    const float* wkp   = (const float*)d_in[2];
    const float* wvop  = (const float*)d_in[3];
    const float* wvarg = (const float*)d_in[4];
    const float* wqs   = (const float*)d_in[5];
    const float* wks   = (const float*)d_in[6];
    const float* wvs   = (const float*)d_in[7];
    float* out = (float*)d_out;

    const int D = in_sizes[1] / 2;   // WQ_prog is (2, D)
    const int T = in_sizes[0] / D;   // embeddings is (T, D)

    if (D == PD && (T % PR) == 0) {
        proj36_kernel<<<T / PR, PTH>>>(emb, wqp, wkp, wvop, wvarg, wqs, wks, wvs, T);
    } else {
        const int pb = (T + 255) / 256;
        proj_generic_kernel<<<pb, 256, (size_t)(11 * D) * sizeof(float)>>>(
            emb, wqp, wkp, wvop, wvarg, wqs, wks, wvs, T, D);
    }

    build_query_kernel<<<NB, BTH>>>(out, T);
}

// round 6
// speedup vs baseline: 2.3567x; 2.3567x over previous
#include <cuda_runtime.h>
#include <float.h>
#include <math.h>

#define MAXT 8192
#define NB   128          // direction bins (one block each in fused kernel)
#define CAP  128          // max candidates per bin (expect ~5-10)

// Scratch (graph-capturable: no allocs; fully overwritten by kernel 1 each launch).
//   g_QQ[i] = { pack(Qprog.x, Qstack.x), pack(Qprog.y, Qstack.y) }
//   g_KK[j] = { pack(Kprog.x, Kstack.x), pack(Kprog.y, Kstack.y) }
//   g_binPS[i] = query i's direction bin, prog in low 16, stack in high 16
__device__ ulonglong2 g_QQ[MAXT], g_KK[MAXT];
__device__ unsigned g_binPS[MAXT];
__device__ float g_Vop[MAXT], g_Varg[MAXT], g_Vstk[MAXT];

__device__ __forceinline__ unsigned long long packf2(float lo, float hi) {
    return ((unsigned long long)__float_as_uint(hi) << 32) | (unsigned long long)__float_as_uint(lo);
}
__device__ __forceinline__ float lo32(unsigned long long v) { return __uint_as_float((unsigned)v); }
__device__ __forceinline__ float hi32(unsigned long long v) { return __uint_as_float((unsigned)(v >> 32)); }

// sm_103a packed fp32 pair math (PTX-only; ptxas won't auto-fuse).
__device__ __forceinline__ unsigned long long mul2(unsigned long long a, unsigned long long b) {
    unsigned long long r;
    asm("mul.rn.f32x2 %0, %1, %2;" : "=l"(r) : "l"(a), "l"(b));
    return r;
}
__device__ __forceinline__ unsigned long long fma2(unsigned long long a, unsigned long long b, unsigned long long c) {
    unsigned long long r;
    asm("fma.rn.f32x2 %0, %1, %2, %3;" : "=l"(r) : "l"(a), "l"(b), "l"(c));
    return r;
}

#define PI_F 3.14159265358979f
#define TWO_PI_F 6.2831853071795865f

__device__ __forceinline__ unsigned qbins(float qpx, float qpy, float qsx, float qsy) {
    const float SC = NB / TWO_PI_F;
    int bP = (int)((atan2f(qpy, qpx) + PI_F) * SC);
    bP = min(max(bP, 0), NB - 1);
    int bS = (int)((atan2f(qsy, qsx) + PI_F) * SC);
    bS = min(max(bS, 0), NB - 1);
    return (unsigned)bP | ((unsigned)bS << 16);
}

// ---------------------------------------------------------------------------
// Kernel 1a: projections specialized for D == 36, plus per-query direction
// bins (computed in the store-latency shadow).
// 32 rows/block, 4 threads/row (9 dims), float4 staging, full unroll.
// ---------------------------------------------------------------------------
#define PD  36
#define PR  32
#define PTH 128

__global__ __launch_bounds__(PTH) void proj36_kernel(
        const float* __restrict__ emb,
        const float* __restrict__ wqp, const float* __restrict__ wkp,
        const float* __restrict__ wvop, const float* __restrict__ wvarg,
        const float* __restrict__ wqs, const float* __restrict__ wks,
        const float* __restrict__ wvs, int T) {
    __shared__ float sw[11 * PD];
    __shared__ float se[PR * PD];
    const int tid = threadIdx.x;

    for (int k = tid; k < 2 * PD; k += PTH) {
        sw[k]          = wqp[k];
        sw[2 * PD + k] = wkp[k];
        sw[4 * PD + k] = wqs[k];
        sw[6 * PD + k] = wks[k];
    }
    if (tid < PD) {
        sw[8 * PD + tid]  = wvop[tid];
        sw[9 * PD + tid]  = wvarg[tid];
        sw[10 * PD + tid] = wvs[tid];
    }

    const int base = blockIdx.x * PR;
    const float4* emb4 = (const float4*)(emb + (size_t)base * PD);
#pragma unroll
    for (int v = 0; v < (PR * PD / 4) / PTH + 1; v++) {
        int idx = tid + v * PTH;
        if (idx < PR * PD / 4) ((float4*)se)[idx] = emb4[idx];
    }
    __syncthreads();

    const int row = tid >> 2, part = tid & 3;
    const float* r0 = se + row * PD + part * 9;

    float rv[9];
#pragma unroll
    for (int dd = 0; dd < 9; dd++) rv[dd] = r0[dd];

    // c: 0=Qp.x 1=Qp.y 2=Kp.x 3=Kp.y 4=Qs.x 5=Qs.y 6=Ks.x 7=Ks.y 8=Vop 9=Varg 10=Vstk
    float a[11];
#pragma unroll
    for (int c = 0; c < 11; c++) a[c] = 0.f;
#pragma unroll
    for (int c = 0; c < 11; c++) {
        const float* wc = sw + c * PD + part * 9;
#pragma unroll
        for (int dd = 0; dd < 9; dd++) a[c] = fmaf(rv[dd], wc[dd], a[c]);
    }
#pragma unroll
    for (int c = 0; c < 11; c++) {
        a[c] += __shfl_down_sync(0xffffffffu, a[c], 1);
        a[c] += __shfl_down_sync(0xffffffffu, a[c], 2);
    }
    if (part == 0) {
        int i = base + row;
        g_QQ[i] = make_ulonglong2(packf2(a[0], a[4]), packf2(a[1], a[5]));
        g_KK[i] = make_ulonglong2(packf2(a[2], a[6]), packf2(a[3], a[7]));
        g_binPS[i] = qbins(a[0], a[1], a[4], a[5]);
        g_Vop[i] = a[8]; g_Varg[i] = a[9]; g_Vstk[i] = a[10];
    }
}

// ---------------------------------------------------------------------------
// Kernel 1b: generic-D fallback (not used for the benchmark shape).
// ---------------------------------------------------------------------------
__global__ void proj_generic_kernel(
        const float* __restrict__ emb,
        const float* __restrict__ wqp, const float* __restrict__ wkp,
        const float* __restrict__ wvop, const float* __restrict__ wvarg,
        const float* __restrict__ wqs, const float* __restrict__ wks,
        const float* __restrict__ wvs, int T, int D) {
    extern __shared__ float sw[];
    const int tid = threadIdx.x;
    for (int k = tid; k < 2 * D; k += blockDim.x) {
        sw[k]         = wqp[k];
        sw[2 * D + k] = wkp[k];
        sw[4 * D + k] = wqs[k];
        sw[6 * D + k] = wks[k];
    }
    for (int k = tid; k < D; k += blockDim.x) {
        sw[8 * D + k]  = wvop[k];
        sw[9 * D + k]  = wvarg[k];
        sw[10 * D + k] = wvs[k];
    }
    __syncthreads();
    int i = blockIdx.x * blockDim.x + tid;
    if (i >= T) return;
    const float* e = emb + (size_t)i * D;
    float a[11];
#pragma unroll
    for (int c = 0; c < 11; c++) a[c] = 0.f;
    for (int d = 0; d < D; d++) {
        float ev = e[d];
#pragma unroll
        for (int c = 0; c < 11; c++) a[c] = fmaf(ev, sw[c * D + d], a[c]);
    }
    g_QQ[i] = make_ulonglong2(packf2(a[0], a[4]), packf2(a[1], a[5]));
    g_KK[i] = make_ulonglong2(packf2(a[2], a[6]), packf2(a[3], a[7]));
    g_binPS[i] = qbins(a[0], a[1], a[4], a[5]);
    g_Vop[i] = a[8]; g_Varg[i] = a[9]; g_Vstk[i] = a[10];
}

// ---------------------------------------------------------------------------
// Kernel 2: fused build + query. One block per direction bin.
//  Phase A (exact max): full scan; max directional score AND max |k|^2 per
//    head along the bin-center direction u (f32x2 packed, fmax only).
//  Phase B (collect): second scan; keep keys with s_u(k) >= M - 1.25*Kmax*DLT
//    into shared memory. Exact-cover guarantee: the argmax key for ANY query
//    direction mapping to this bin satisfies s_u >= M - Kmax*DLT (two
//    Lipschitz terms of Kmax*DLT/2); the 1.25 inflation absorbs fp slop.
//    (Round-3/4-proven construction; the round-5 subsample shortcut is what
//    broke the candidate count and is reverted here.)
//  Phase C (query): scan per-query bins; resolve this bin's queries against
//    the smem candidate list with exact fp32 scores + first-index tie-break
//    (order-independent, matches jnp.argmax).
// ---------------------------------------------------------------------------
#define BTH 512
#define NW  (BTH / 32)

__global__ __launch_bounds__(BTH) void build_query_kernel(float* __restrict__ out, int T) {
    __shared__ int scandP[CAP], scandS[CAP];
    __shared__ int scnt[2];
    __shared__ float sred[4][NW];
    __shared__ float sth[2];

    const int b = blockIdx.x;
    const int tid = threadIdx.x, lane = tid & 31, w = tid >> 5;
    const float DLT = TWO_PI_F / NB;
    const float th = -PI_F + (b + 0.5f) * DLT;
    const float ux = cosf(th), uy = sinf(th);
    const unsigned long long ua = packf2(ux, ux), ub = packf2(uy, uy);

    // ---- phase A: exact max of s and |k|^2 (both heads packed) ----
    float v[4] = {-FLT_MAX, -FLT_MAX, 0.f, 0.f};   // maxP, maxS, n2P, n2S
#pragma unroll 4
    for (int j = tid; j < T; j += BTH) {
        ulonglong2 kk = g_KK[j];
        unsigned long long s  = fma2(ua, kk.x, mul2(ub, kk.y));
        unsigned long long n2 = fma2(kk.x, kk.x, mul2(kk.y, kk.y));
        v[0] = fmaxf(v[0], lo32(s));  v[1] = fmaxf(v[1], hi32(s));
        v[2] = fmaxf(v[2], lo32(n2)); v[3] = fmaxf(v[3], hi32(n2));
    }
#pragma unroll
    for (int c = 0; c < 4; c++) {
#pragma unroll
        for (int off = 16; off; off >>= 1)
            v[c] = fmaxf(v[c], __shfl_xor_sync(0xffffffffu, v[c], off));
        if (lane == 0) sred[c][w] = v[c];
    }
    if (tid < 2) scnt[tid] = 0;
    __syncthreads();
    if (tid < 2) {
        float M = sred[tid][0], N2 = sred[2 + tid][0];
#pragma unroll
        for (int k = 1; k < NW; k++) {
            M = fmaxf(M, sred[tid][k]);
            N2 = fmaxf(N2, sred[2 + tid][k]);
        }
        sth[tid] = M - 1.25f * sqrtf(N2) * DLT;
    }
    __syncthreads();
    const float tP = sth[0], tS = sth[1];

    // ---- phase B: collect candidates into smem ----
#pragma unroll 4
    for (int j = tid; j < T; j += BTH) {
        ulonglong2 kk = g_KK[j];
        unsigned long long s = fma2(ua, kk.x, mul2(ub, kk.y));
        if (lo32(s) >= tP) { int p = atomicAdd(&scnt[0], 1); if (p < CAP) scandP[p] = j; }
        if (hi32(s) >= tS) { int p = atomicAdd(&scnt[1], 1); if (p < CAP) scandS[p] = j; }
    }
    __syncthreads();
    const int nP = min(scnt[0], CAP), nS = min(scnt[1], CAP);

    // ---- phase C: resolve this bin's queries ----
    for (int j = tid; j < T; j += BTH) {
        const unsigned bp = g_binPS[j];
        const bool doP = ((bp & 0xffffu) == (unsigned)b);
        const bool doS = ((bp >> 16) == (unsigned)b);
        if (doP || doS) {
            ulonglong2 q = g_QQ[j];
            if (doP) {
                const float qx = lo32(q.x), qy = lo32(q.y);
                float best = -FLT_MAX; int bi = 0x7fffffff;
                for (int t = 0; t < nP; t++) {
                    int c = scandP[t];
                    ulonglong2 k2 = g_KK[c];
                    float sc = fmaf(qx, lo32(k2.x), __fmul_rn(qy, lo32(k2.y)));
                    if (sc > best || (sc == best && c < bi)) { best = sc; bi = c; }
                }
                out[j]     = g_Vop[bi];
                out[T + j] = g_Varg[bi];
            }
            if (doS) {
                const float qx = hi32(q.x), qy = hi32(q.y);
                float best = -FLT_MAX; int bi = 0x7fffffff;
                for (int t = 0; t < nS; t++) {
                    int c = scandS[t];
                    ulonglong2 k2 = g_KK[c];
                    float sc = fmaf(qx, hi32(k2.x), __fmul_rn(qy, hi32(k2.y)));
                    if (sc > best || (sc == best && c < bi)) { best = sc; bi = c; }
                }
                out[2 * T + j] = g_Vstk[bi];
            }
        }
    }
}

extern "C" void kernel_launch(void* const* d_in, const int* in_sizes, int n_in,
                              void* d_out, int out_size) {
    const float* emb   = (const float*)d_in[0];
    const float* wqp   = (const float*)d_in[1];
    const float* wkp   = (const float*)d_in[2];
    const float* wvop  = (const float*)d_in[3];
    const float* wvarg = (const float*)d_in[4];
    const float* wqs   = (const float*)d_in[5];
    const float* wks   = (const float*)d_in[6];
    const float* wvs   = (const float*)d_in[7];
    float* out = (float*)d_out;

    const int D = in_sizes[1] / 2;   // WQ_prog is (2, D)
    const int T = in_sizes[0] / D;   // embeddings is (T, D)

    if (D == PD && (T % PR) == 0) {
        proj36_kernel<<<T / PR, PTH>>>(emb, wqp, wkp, wvop, wvarg, wqs, wks, wvs, T);
    } else {
        const int pb = (T + 255) / 256;
        proj_generic_kernel<<<pb, 256, (size_t)(11 * D) * sizeof(float)>>>(
            emb, wqp, wkp, wvop, wvarg, wqs, wks, wvs, T, D);
    }

    build_query_kernel<<<NB, BTH>>>(out, T);
}

// round 7
// speedup vs baseline: 2.4618x; 1.0446x over previous
#include <cuda_runtime.h>
#include <float.h>
#include <math.h>

#define MAXT 8192
#define NB   128          // direction bins (one block each in fused kernel)
#define CAP  128          // max key candidates per bin (expect ~2-8)
#define CAPQ 384          // max queries per bin list (expect ~64; fallback if over)

// Scratch (graph-capturable: no allocs). g_qcnt is zeroed by a captured
// memset node each launch; everything else is fully rewritten by kernel 1.
__device__ ulonglong2 g_QQ[MAXT], g_KK[MAXT];
__device__ unsigned g_binPS[MAXT];
__device__ float g_Vop[MAXT], g_Varg[MAXT], g_Vstk[MAXT];
__device__ int g_qcnt[2 * NB];                 // [0,NB)=prog, [NB,2NB)=stack
__device__ int g_qlistP[NB * CAPQ], g_qlistS[NB * CAPQ];

__device__ __forceinline__ unsigned long long packf2(float lo, float hi) {
    return ((unsigned long long)__float_as_uint(hi) << 32) | (unsigned long long)__float_as_uint(lo);
}
__device__ __forceinline__ float lo32(unsigned long long v) { return __uint_as_float((unsigned)v); }
__device__ __forceinline__ float hi32(unsigned long long v) { return __uint_as_float((unsigned)(v >> 32)); }

// sm_103a packed fp32 pair math (PTX-only; ptxas won't auto-fuse).
__device__ __forceinline__ unsigned long long mul2(unsigned long long a, unsigned long long b) {
    unsigned long long r;
    asm("mul.rn.f32x2 %0, %1, %2;" : "=l"(r) : "l"(a), "l"(b));
    return r;
}
__device__ __forceinline__ unsigned long long fma2(unsigned long long a, unsigned long long b, unsigned long long c) {
    unsigned long long r;
    asm("fma.rn.f32x2 %0, %1, %2, %3;" : "=l"(r) : "l"(a), "l"(b), "l"(c));
    return r;
}

#define PI_F 3.14159265358979f
#define TWO_PI_F 6.2831853071795865f

__device__ __forceinline__ unsigned qbins(float qpx, float qpy, float qsx, float qsy) {
    const float SC = NB / TWO_PI_F;
    int bP = (int)((atan2f(qpy, qpx) + PI_F) * SC);
    bP = min(max(bP, 0), NB - 1);
    int bS = (int)((atan2f(qsy, qsx) + PI_F) * SC);
    bS = min(max(bS, 0), NB - 1);
    return (unsigned)bP | ((unsigned)bS << 16);
}

__device__ __forceinline__ void push_query(int i, unsigned bp) {
    const int bP = (int)(bp & 0xffffu), bS = (int)(bp >> 16);
    int p = atomicAdd(&g_qcnt[bP], 1);
    if (p < CAPQ) g_qlistP[bP * CAPQ + p] = i;
    int s = atomicAdd(&g_qcnt[NB + bS], 1);
    if (s < CAPQ) g_qlistS[bS * CAPQ + s] = i;
}

// ---------------------------------------------------------------------------
// Kernel 1a: projections specialized for D == 36; also computes each query's
// direction bin and appends the query id to that bin's list (atomics in the
// store-latency shadow).
// ---------------------------------------------------------------------------
#define PD  36
#define PR  32
#define PTH 128

__global__ __launch_bounds__(PTH) void proj36_kernel(
        const float* __restrict__ emb,
        const float* __restrict__ wqp, const float* __restrict__ wkp,
        const float* __restrict__ wvop, const float* __restrict__ wvarg,
        const float* __restrict__ wqs, const float* __restrict__ wks,
        const float* __restrict__ wvs, int T) {
    __shared__ float sw[11 * PD];
    __shared__ float se[PR * PD];
    const int tid = threadIdx.x;

    for (int k = tid; k < 2 * PD; k += PTH) {
        sw[k]          = wqp[k];
        sw[2 * PD + k] = wkp[k];
        sw[4 * PD + k] = wqs[k];
        sw[6 * PD + k] = wks[k];
    }
    if (tid < PD) {
        sw[8 * PD + tid]  = wvop[tid];
        sw[9 * PD + tid]  = wvarg[tid];
        sw[10 * PD + tid] = wvs[tid];
    }

    const int base = blockIdx.x * PR;
    const float4* emb4 = (const float4*)(emb + (size_t)base * PD);
#pragma unroll
    for (int v = 0; v < (PR * PD / 4) / PTH + 1; v++) {
        int idx = tid + v * PTH;
        if (idx < PR * PD / 4) ((float4*)se)[idx] = emb4[idx];
    }
    __syncthreads();

    const int row = tid >> 2, part = tid & 3;
    const float* r0 = se + row * PD + part * 9;

    float rv[9];
#pragma unroll
    for (int dd = 0; dd < 9; dd++) rv[dd] = r0[dd];

    // c: 0=Qp.x 1=Qp.y 2=Kp.x 3=Kp.y 4=Qs.x 5=Qs.y 6=Ks.x 7=Ks.y 8=Vop 9=Varg 10=Vstk
    float a[11];
#pragma unroll
    for (int c = 0; c < 11; c++) a[c] = 0.f;
#pragma unroll
    for (int c = 0; c < 11; c++) {
        const float* wc = sw + c * PD + part * 9;
#pragma unroll
        for (int dd = 0; dd < 9; dd++) a[c] = fmaf(rv[dd], wc[dd], a[c]);
    }
#pragma unroll
    for (int c = 0; c < 11; c++) {
        a[c] += __shfl_down_sync(0xffffffffu, a[c], 1);
        a[c] += __shfl_down_sync(0xffffffffu, a[c], 2);
    }
    if (part == 0) {
        int i = base + row;
        g_QQ[i] = make_ulonglong2(packf2(a[0], a[4]), packf2(a[1], a[5]));
        g_KK[i] = make_ulonglong2(packf2(a[2], a[6]), packf2(a[3], a[7]));
        unsigned bp = qbins(a[0], a[1], a[4], a[5]);
        g_binPS[i] = bp;
        g_Vop[i] = a[8]; g_Varg[i] = a[9]; g_Vstk[i] = a[10];
        push_query(i, bp);
    }
}

// ---------------------------------------------------------------------------
// Kernel 1b: generic-D fallback (not used for the benchmark shape).
// ---------------------------------------------------------------------------
__global__ void proj_generic_kernel(
        const float* __restrict__ emb,
        const float* __restrict__ wqp, const float* __restrict__ wkp,
        const float* __restrict__ wvop, const float* __restrict__ wvarg,
        const float* __restrict__ wqs, const float* __restrict__ wks,
        const float* __restrict__ wvs, int T, int D) {
    extern __shared__ float sw[];
    const int tid = threadIdx.x;
    for (int k = tid; k < 2 * D; k += blockDim.x) {
        sw[k]         = wqp[k];
        sw[2 * D + k] = wkp[k];
        sw[4 * D + k] = wqs[k];
        sw[6 * D + k] = wks[k];
    }
    for (int k = tid; k < D; k += blockDim.x) {
        sw[8 * D + k]  = wvop[k];
        sw[9 * D + k]  = wvarg[k];
        sw[10 * D + k] = wvs[k];
    }
    __syncthreads();
    int i = blockIdx.x * blockDim.x + tid;
    if (i >= T) return;
    const float* e = emb + (size_t)i * D;
    float a[11];
#pragma unroll
    for (int c = 0; c < 11; c++) a[c] = 0.f;
    for (int d = 0; d < D; d++) {
        float ev = e[d];
#pragma unroll
        for (int c = 0; c < 11; c++) a[c] = fmaf(ev, sw[c * D + d], a[c]);
    }
    g_QQ[i] = make_ulonglong2(packf2(a[0], a[4]), packf2(a[1], a[5]));
    g_KK[i] = make_ulonglong2(packf2(a[2], a[6]), packf2(a[3], a[7]));
    unsigned bp = qbins(a[0], a[1], a[4], a[5]);
    g_binPS[i] = bp;
    g_Vop[i] = a[8]; g_Varg[i] = a[9]; g_Vstk[i] = a[10];
    push_query(i, bp);
}

// ---------------------------------------------------------------------------
// Kernel 2: fused build + query, one block per bin.
//  Phase 0: SINGLE global scan: stage all keys into dynamic smem while
//    computing the exact per-head max score and max |k|^2 along the
//    bin-center direction u (round-4-proven exact threshold construction:
//    thresh = M - 1.25*Kmax*DLT covers the argmax of every direction in bin).
//  Phase B: collect candidates scanning SMEM (cheap), prefetch their V.
//  Phase C: resolve only this bin's queries from the per-bin list built by
//    kernel 1 (avg ~T/NB per head). Exact fp32 scores, first-index tie-break
//    (order-independent => matches jnp.argmax). If a list overflowed CAPQ,
//    fall back to an exact g_binPS rescan for this bin (idempotent rewrites).
// ---------------------------------------------------------------------------
#define BTH 512
#define NW  (BTH / 32)

extern __shared__ ulonglong2 sKK[];   // [MAXT] staged keys

__global__ __launch_bounds__(BTH) void build_query_kernel(float* __restrict__ out, int T) {
    __shared__ int scandP[CAP], scandS[CAP];
    __shared__ float sVop[CAP], sVarg[CAP], sVstk[CAP];
    __shared__ int scnt[2];
    __shared__ float sred[4][NW];
    __shared__ float sth[2];

    const int b = blockIdx.x;
    const int tid = threadIdx.x, lane = tid & 31, w = tid >> 5;
    const float DLT = TWO_PI_F / NB;
    const float th = -PI_F + (b + 0.5f) * DLT;
    const float ux = cosf(th), uy = sinf(th);
    const unsigned long long ua = packf2(ux, ux), ub = packf2(uy, uy);

    // ---- phase 0: stage keys to smem + exact max of s and |k|^2 ----
    float v[4] = {-FLT_MAX, -FLT_MAX, 0.f, 0.f};   // maxP, maxS, n2P, n2S
#pragma unroll 4
    for (int j = tid; j < T; j += BTH) {
        ulonglong2 kk = g_KK[j];
        sKK[j] = kk;
        unsigned long long s  = fma2(ua, kk.x, mul2(ub, kk.y));
        unsigned long long n2 = fma2(kk.x, kk.x, mul2(kk.y, kk.y));
        v[0] = fmaxf(v[0], lo32(s));  v[1] = fmaxf(v[1], hi32(s));
        v[2] = fmaxf(v[2], lo32(n2)); v[3] = fmaxf(v[3], hi32(n2));
    }
#pragma unroll
    for (int c = 0; c < 4; c++) {
#pragma unroll
        for (int off = 16; off; off >>= 1)
            v[c] = fmaxf(v[c], __shfl_xor_sync(0xffffffffu, v[c], off));
        if (lane == 0) sred[c][w] = v[c];
    }
    if (tid < 2) scnt[tid] = 0;
    __syncthreads();
    if (tid < 2) {
        float M = sred[tid][0], N2 = sred[2 + tid][0];
#pragma unroll
        for (int k = 1; k < NW; k++) {
            M = fmaxf(M, sred[tid][k]);
            N2 = fmaxf(N2, sred[2 + tid][k]);
        }
        sth[tid] = M - 1.25f * sqrtf(N2) * DLT;
    }
    __syncthreads();
    const float tP = sth[0], tS = sth[1];

    // ---- phase B: collect candidates from SMEM ----
#pragma unroll 4
    for (int j = tid; j < T; j += BTH) {
        ulonglong2 kk = sKK[j];
        unsigned long long s = fma2(ua, kk.x, mul2(ub, kk.y));
        if (lo32(s) >= tP) { int p = atomicAdd(&scnt[0], 1); if (p < CAP) scandP[p] = j; }
        if (hi32(s) >= tS) { int p = atomicAdd(&scnt[1], 1); if (p < CAP) scandS[p] = j; }
    }
    __syncthreads();
    const int nP = min(scnt[0], CAP), nS = min(scnt[1], CAP);
    // prefetch candidate V into smem
    for (int t = tid; t < nP; t += BTH) {
        int c = scandP[t];
        sVop[t] = g_Vop[c]; sVarg[t] = g_Varg[c];
    }
    for (int t = tid; t < nS; t += BTH) sVstk[t] = g_Vstk[scandS[t]];
    __syncthreads();

    // ---- phase C: resolve this bin's queries from the per-bin lists ----
    const int totP = g_qcnt[b], totS = g_qcnt[NB + b];
    const int nqP = min(totP, CAPQ), nqS = min(totS, CAPQ);

    for (int t = tid; t < nqP; t += BTH) {
        const int i = g_qlistP[b * CAPQ + t];
        ulonglong2 q = g_QQ[i];
        const float qx = lo32(q.x), qy = lo32(q.y);
        float best = -FLT_MAX; int bi = 0x7fffffff, bt = 0;
        for (int c = 0; c < nP; c++) {
            int kj = scandP[c];
            ulonglong2 k2 = sKK[kj];
            float sc = fmaf(qx, lo32(k2.x), __fmul_rn(qy, lo32(k2.y)));
            if (sc > best || (sc == best && kj < bi)) { best = sc; bi = kj; bt = c; }
        }
        out[i]     = sVop[bt];
        out[T + i] = sVarg[bt];
    }
    for (int t = tid; t < nqS; t += BTH) {
        const int i = g_qlistS[b * CAPQ + t];
        ulonglong2 q = g_QQ[i];
        const float qx = hi32(q.x), qy = hi32(q.y);
        float best = -FLT_MAX; int bi = 0x7fffffff, bt = 0;
        for (int c = 0; c < nS; c++) {
            int kj = scandS[c];
            ulonglong2 k2 = sKK[kj];
            float sc = fmaf(qx, hi32(k2.x), __fmul_rn(qy, hi32(k2.y)));
            if (sc > best || (sc == best && kj < bi)) { best = sc; bi = kj; bt = c; }
        }
        out[2 * T + i] = sVstk[bt];
    }

    // ---- exact fallback if a query list overflowed (never expected) ----
    if (totP > CAPQ) {
        for (int j = tid; j < T; j += BTH) {
            if ((g_binPS[j] & 0xffffu) == (unsigned)b) {
                ulonglong2 q = g_QQ[j];
                const float qx = lo32(q.x), qy = lo32(q.y);
                float best = -FLT_MAX; int bi = 0x7fffffff, bt = 0;
                for (int c = 0; c < nP; c++) {
                    int kj = scandP[c];
                    ulonglong2 k2 = sKK[kj];
                    float sc = fmaf(qx, lo32(k2.x), __fmul_rn(qy, lo32(k2.y)));
                    if (sc > best || (sc == best && kj < bi)) { best = sc; bi = kj; bt = c; }
                }
                out[j]     = sVop[bt];
                out[T + j] = sVarg[bt];
            }
        }
    }
    if (totS > CAPQ) {
        for (int j = tid; j < T; j += BTH) {
            if ((g_binPS[j] >> 16) == (unsigned)b) {
                ulonglong2 q = g_QQ[j];
                const float qx = hi32(q.x), qy = hi32(q.y);
                float best = -FLT_MAX; int bi = 0x7fffffff, bt = 0;
                for (int c = 0; c < nS; c++) {
                    int kj = scandS[c];
                    ulonglong2 k2 = sKK[kj];
                    float sc = fmaf(qx, hi32(k2.x), __fmul_rn(qy, hi32(k2.y)));
                    if (sc > best || (sc == best && kj < bi)) { best = sc; bi = kj; bt = c; }
                }
                out[2 * T + j] = sVstk[bt];
            }
        }
    }
}

extern "C" void kernel_launch(void* const* d_in, const int* in_sizes, int n_in,
                              void* d_out, int out_size) {
    const float* emb   = (const float*)d_in[0];
    const float* wqp   = (const float*)d_in[1];
    const float* wkp   = (const float*)d_in[2];
    const float* wvop  = (const float*)d_in[3];
    const float* wvarg = (const float*)d_in[4];
    const float* wqs   = (const float*)d_in[5];
    const float* wks   = (const float*)d_in[6];
    const float* wvs   = (const float*)d_in[7];
    float* out = (float*)d_out;

    const int D = in_sizes[1] / 2;   // WQ_prog is (2, D)
    const int T = in_sizes[0] / D;   // embeddings is (T, D)

    // zero the per-bin query counters (captured as a memset node)
    void* qcnt_ptr = nullptr;
    cudaGetSymbolAddress(&qcnt_ptr, g_qcnt);
    cudaMemsetAsync(qcnt_ptr, 0, sizeof(int) * 2 * NB, 0);

    if (D == PD && (T % PR) == 0) {
        proj36_kernel<<<T / PR, PTH>>>(emb, wqp, wkp, wvop, wvarg, wqs, wks, wvs, T);
    } else {
        const int pb = (T + 255) / 256;
        proj_generic_kernel<<<pb, 256, (size_t)(11 * D) * sizeof(float)>>>(
            emb, wqp, wkp, wvop, wvarg, wqs, wks, wvs, T, D);
    }

    // opt-in to 128KB dynamic smem for the key cache (idempotent host call)
    static_assert(MAXT * sizeof(ulonglong2) == 131072, "smem size");
    cudaFuncSetAttribute(build_query_kernel,
                         cudaFuncAttributeMaxDynamicSharedMemorySize,
                         MAXT * sizeof(ulonglong2));
    build_query_kernel<<<NB, BTH, MAXT * sizeof(ulonglong2)>>>(out, T);
}

// round 8
// speedup vs baseline: 2.5767x; 1.0467x over previous
#include <cuda_runtime.h>
#include <float.h>
#include <math.h>

#define MAXT 8192
#define NB   128          // direction bins == grid size of mega kernel
#define CAP  128          // max key candidates per bin (expect ~2-8)
#define CAPQ 384          // max queries per bin list (expect ~64; exact fallback if over)
#define BTH  512
#define NWRP (BTH / 32)
#define PD   36
#define RPB  (MAXT / NB)  // 64 rows projected per block

// Device scratch (graph-capturable: no allocs). g_qcnt is self-resetting
// (each block zeroes its own bins after use; zero-initialized at load).
// g_bar is a cumulative device-wide barrier counter (monotone across
// launches; target derived from its own value => launch-agnostic).
__device__ ulonglong2 g_QQ[MAXT], g_KK[MAXT];
__device__ unsigned g_binPS[MAXT];
__device__ float g_Vop[MAXT], g_Varg[MAXT], g_Vstk[MAXT];
__device__ int g_qcnt[2 * NB];                 // [0,NB)=prog, [NB,2NB)=stack
__device__ int g_qlistP[NB * CAPQ], g_qlistS[NB * CAPQ];
__device__ unsigned int g_bar;

__device__ __forceinline__ unsigned long long packf2(float lo, float hi) {
    return ((unsigned long long)__float_as_uint(hi) << 32) | (unsigned long long)__float_as_uint(lo);
}
__device__ __forceinline__ float lo32(unsigned long long v) { return __uint_as_float((unsigned)v); }
__device__ __forceinline__ float hi32(unsigned long long v) { return __uint_as_float((unsigned)(v >> 32)); }

// sm_103a packed fp32 pair math (PTX-only; ptxas won't auto-fuse).
__device__ __forceinline__ unsigned long long mul2(unsigned long long a, unsigned long long b) {
    unsigned long long r;
    asm("mul.rn.f32x2 %0, %1, %2;" : "=l"(r) : "l"(a), "l"(b));
    return r;
}
__device__ __forceinline__ unsigned long long fma2(unsigned long long a, unsigned long long b, unsigned long long c) {
    unsigned long long r;
    asm("fma.rn.f32x2 %0, %1, %2, %3;" : "=l"(r) : "l"(a), "l"(b), "l"(c));
    return r;
}

#define PI_F 3.14159265358979f
#define TWO_PI_F 6.2831853071795865f

__device__ __forceinline__ unsigned qbins(float qpx, float qpy, float qsx, float qsy) {
    const float SC = NB / TWO_PI_F;
    int bP = (int)((atan2f(qpy, qpx) + PI_F) * SC);
    bP = min(max(bP, 0), NB - 1);
    int bS = (int)((atan2f(qsy, qsx) + PI_F) * SC);
    bS = min(max(bS, 0), NB - 1);
    return (unsigned)bP | ((unsigned)bS << 16);
}

__device__ __forceinline__ void push_query(int i, unsigned bp) {
    const int bP = (int)(bp & 0xffffu), bS = (int)(bp >> 16);
    int p = atomicAdd(&g_qcnt[bP], 1);
    if (p < CAPQ) g_qlistP[bP * CAPQ + p] = i;
    int s = atomicAdd(&g_qcnt[NB + bS], 1);
    if (s < CAPQ) g_qlistS[bS * CAPQ + s] = i;
}

// Device-wide barrier. Valid because grid (128) <= SM count (148+): all
// blocks are resident in wave 1. Cumulative counter: each launch adds
// exactly gridDim.x; a block rounds its arrival up to the next multiple of
// gridDim.x and spins until reached. No reset needed across graph replays.
__device__ __forceinline__ void grid_sync() {
    __syncthreads();
    __threadfence();
    if (threadIdx.x == 0) {
        const unsigned G = gridDim.x;
        unsigned t = atomicAdd(&g_bar, 1u);
        unsigned target = (t / G + 1u) * G;
        while (atomicAdd(&g_bar, 0u) < target) { __nanosleep(64); }
    }
    __syncthreads();
    __threadfence();
}

// ---------------------------------------------------------------------------
// MEGA kernel (D==36, T==MAXT): proj + bin-filter build + query in one
// launch, one device-wide sync. One block per direction bin.
// ---------------------------------------------------------------------------
__global__ __launch_bounds__(BTH) void mega_kernel(
        const float* __restrict__ emb,
        const float* __restrict__ wqp, const float* __restrict__ wkp,
        const float* __restrict__ wvop, const float* __restrict__ wvarg,
        const float* __restrict__ wqs, const float* __restrict__ wks,
        const float* __restrict__ wvs, float* __restrict__ out) {
    extern __shared__ unsigned char s_dyn[];   // 128 KB, reused across phases
    __shared__ int scandP[CAP], scandS[CAP];
    __shared__ float sVop[CAP], sVarg[CAP], sVstk[CAP];
    __shared__ int scnt[2];
    __shared__ float sred[4][NWRP];
    __shared__ float sth[2];

    const int b = blockIdx.x;
    const int tid = threadIdx.x, lane = tid & 31, w = tid >> 5;
    const int T = MAXT;

    // ================= phase 1: project rows [b*RPB, (b+1)*RPB) ============
    {
        float* sw = (float*)s_dyn;            // 11*PD floats
        float* se = sw + 11 * PD;             // RPB*PD floats

        for (int k = tid; k < 2 * PD; k += BTH) {
            sw[k]          = wqp[k];
            sw[2 * PD + k] = wkp[k];
            sw[4 * PD + k] = wqs[k];
            sw[6 * PD + k] = wks[k];
        }
        if (tid < PD) {
            sw[8 * PD + tid]  = wvop[tid];
            sw[9 * PD + tid]  = wvarg[tid];
            sw[10 * PD + tid] = wvs[tid];
        }
        const int base = b * RPB;
        const float4* emb4 = (const float4*)(emb + (size_t)base * PD);
        if (tid < RPB * PD / 4) ((float4*)se)[tid] = emb4[tid];   // 576 <= BTH? no: 576 > 512
        {   // remainder of the 576 float4 stage
            int idx = tid + BTH;
            if (idx < RPB * PD / 4) ((float4*)se)[idx] = emb4[idx];
        }
        __syncthreads();

        if (tid < RPB * 4) {
            const int row = tid >> 2, part = tid & 3;
            const float* r0 = se + row * PD + part * 9;
            float rv[9];
#pragma unroll
            for (int dd = 0; dd < 9; dd++) rv[dd] = r0[dd];

            // c: 0=Qp.x 1=Qp.y 2=Kp.x 3=Kp.y 4=Qs.x 5=Qs.y 6=Ks.x 7=Ks.y 8=Vop 9=Varg 10=Vstk
            float a[11];
#pragma unroll
            for (int c = 0; c < 11; c++) a[c] = 0.f;
#pragma unroll
            for (int c = 0; c < 11; c++) {
                const float* wc = sw + c * PD + part * 9;
#pragma unroll
                for (int dd = 0; dd < 9; dd++) a[c] = fmaf(rv[dd], wc[dd], a[c]);
            }
#pragma unroll
            for (int c = 0; c < 11; c++) {
                a[c] += __shfl_down_sync(0xffffffffu, a[c], 1);
                a[c] += __shfl_down_sync(0xffffffffu, a[c], 2);
            }
            if (part == 0) {
                int i = base + row;
                g_QQ[i] = make_ulonglong2(packf2(a[0], a[4]), packf2(a[1], a[5]));
                g_KK[i] = make_ulonglong2(packf2(a[2], a[6]), packf2(a[3], a[7]));
                unsigned bp = qbins(a[0], a[1], a[4], a[5]);
                g_binPS[i] = bp;
                g_Vop[i] = a[8]; g_Varg[i] = a[9]; g_Vstk[i] = a[10];
                push_query(i, bp);
            }
        }
    }

    // ================= device-wide sync =====================================
    grid_sync();

    // ================= phase 2: stage keys + exact threshold ================
    ulonglong2* sKK = (ulonglong2*)s_dyn;     // reuse (all blocks past phase 1)
    const float DLT = TWO_PI_F / NB;
    const float thb = -PI_F + (b + 0.5f) * DLT;
    const float ux = cosf(thb), uy = sinf(thb);
    const unsigned long long ua = packf2(ux, ux), ub = packf2(uy, uy);

    float v[4] = {-FLT_MAX, -FLT_MAX, 0.f, 0.f};   // maxP, maxS, n2P, n2S
#pragma unroll
    for (int g = 0; g < MAXT / BTH / 8; g++) {      // 2 groups x 8-wide MLP
        ulonglong2 kb[8];
#pragma unroll
        for (int u = 0; u < 8; u++) kb[u] = g_KK[tid + (g * 8 + u) * BTH];
#pragma unroll
        for (int u = 0; u < 8; u++) {
            const int j = tid + (g * 8 + u) * BTH;
            sKK[j] = kb[u];
            unsigned long long s  = fma2(ua, kb[u].x, mul2(ub, kb[u].y));
            unsigned long long n2 = fma2(kb[u].x, kb[u].x, mul2(kb[u].y, kb[u].y));
            v[0] = fmaxf(v[0], lo32(s));  v[1] = fmaxf(v[1], hi32(s));
            v[2] = fmaxf(v[2], lo32(n2)); v[3] = fmaxf(v[3], hi32(n2));
        }
    }
#pragma unroll
    for (int c = 0; c < 4; c++) {
#pragma unroll
        for (int off = 16; off; off >>= 1)
            v[c] = fmaxf(v[c], __shfl_xor_sync(0xffffffffu, v[c], off));
        if (lane == 0) sred[c][w] = v[c];
    }
    if (tid < 2) scnt[tid] = 0;
    __syncthreads();
    if (tid < 2) {
        float M = sred[tid][0], N2 = sred[2 + tid][0];
#pragma unroll
        for (int k = 1; k < NWRP; k++) {
            M = fmaxf(M, sred[tid][k]);
            N2 = fmaxf(N2, sred[2 + tid][k]);
        }
        // Exact-cover threshold (round-4-proven): argmax key of any direction
        // in this bin has s_u >= M - Kmax*DLT; 1.25 inflation absorbs fp slop.
        sth[tid] = M - 1.25f * sqrtf(N2) * DLT;
    }
    __syncthreads();
    const float tP = sth[0], tS = sth[1];

    // ================= phase B: collect candidates from smem ================
#pragma unroll 4
    for (int j = tid; j < T; j += BTH) {
        ulonglong2 kk = sKK[j];
        unsigned long long s = fma2(ua, kk.x, mul2(ub, kk.y));
        if (lo32(s) >= tP) { int p = atomicAdd(&scnt[0], 1); if (p < CAP) scandP[p] = j; }
        if (hi32(s) >= tS) { int p = atomicAdd(&scnt[1], 1); if (p < CAP) scandS[p] = j; }
    }
    __syncthreads();
    const int nP = min(scnt[0], CAP), nS = min(scnt[1], CAP);
    for (int t = tid; t < nP; t += BTH) {
        int c = scandP[t];
        sVop[t] = g_Vop[c]; sVarg[t] = g_Varg[c];
    }
    for (int t = tid; t < nS; t += BTH) sVstk[t] = g_Vstk[scandS[t]];
    __syncthreads();

    // ================= phase C: resolve this bin's queries ==================
    const int totP = g_qcnt[b], totS = g_qcnt[NB + b];
    const int nqP = min(totP, CAPQ), nqS = min(totS, CAPQ);

    for (int t = tid; t < nqP; t += BTH) {
        const int i = g_qlistP[b * CAPQ + t];
        ulonglong2 q = g_QQ[i];
        const float qx = lo32(q.x), qy = lo32(q.y);
        float best = -FLT_MAX; int bi = 0x7fffffff, bt = 0;
        for (int c = 0; c < nP; c++) {
            int kj = scandP[c];
            ulonglong2 k2 = sKK[kj];
            float sc = fmaf(qx, lo32(k2.x), __fmul_rn(qy, lo32(k2.y)));
            if (sc > best || (sc == best && kj < bi)) { best = sc; bi = kj; bt = c; }
        }
        out[i]     = sVop[bt];
        out[T + i] = sVarg[bt];
    }
    for (int t = tid; t < nqS; t += BTH) {
        const int i = g_qlistS[b * CAPQ + t];
        ulonglong2 q = g_QQ[i];
        const float qx = hi32(q.x), qy = hi32(q.y);
        float best = -FLT_MAX; int bi = 0x7fffffff, bt = 0;
        for (int c = 0; c < nS; c++) {
            int kj = scandS[c];
            ulonglong2 k2 = sKK[kj];
            float sc = fmaf(qx, hi32(k2.x), __fmul_rn(qy, hi32(k2.y)));
            if (sc > best || (sc == best && kj < bi)) { best = sc; bi = kj; bt = c; }
        }
        out[2 * T + i] = sVstk[bt];
    }

    // exact fallback if a query list overflowed (never expected; idempotent)
    if (totP > CAPQ) {
        for (int j = tid; j < T; j += BTH) {
            if ((g_binPS[j] & 0xffffu) == (unsigned)b) {
                ulonglong2 q = g_QQ[j];
                const float qx = lo32(q.x), qy = lo32(q.y);
                float best = -FLT_MAX; int bi = 0x7fffffff, bt = 0;
                for (int c = 0; c < nP; c++) {
                    int kj = scandP[c];
                    ulonglong2 k2 = sKK[kj];
                    float sc = fmaf(qx, lo32(k2.x), __fmul_rn(qy, lo32(k2.y)));
                    if (sc > best || (sc == best && kj < bi)) { best = sc; bi = kj; bt = c; }
                }
                out[j]     = sVop[bt];
                out[T + j] = sVarg[bt];
            }
        }
    }
    if (totS > CAPQ) {
        for (int j = tid; j < T; j += BTH) {
            if ((g_binPS[j] >> 16) == (unsigned)b) {
                ulonglong2 q = g_QQ[j];
                const float qx = hi32(q.x), qy = hi32(q.y);
                float best = -FLT_MAX; int bi = 0x7fffffff, bt = 0;
                for (int c = 0; c < nS; c++) {
                    int kj = scandS[c];
                    ulonglong2 k2 = sKK[kj];
                    float sc = fmaf(qx, hi32(k2.x), __fmul_rn(qy, hi32(k2.y)));
                    if (sc > best || (sc == best && kj < bi)) { best = sc; bi = kj; bt = c; }
                }
                out[2 * T + j] = sVstk[bt];
            }
        }
    }

    // self-reset this bin's query counters for the next launch
    __syncthreads();
    if (tid == 0) { g_qcnt[b] = 0; g_qcnt[NB + b] = 0; }
}

// ---------------------------------------------------------------------------
// Generic fallback path (D != 36 or T != MAXT): round-7 three-kernel pipeline.
// ---------------------------------------------------------------------------
__global__ void proj_generic_kernel(
        const float* __restrict__ emb,
        const float* __restrict__ wqp, const float* __restrict__ wkp,
        const float* __restrict__ wvop, const float* __restrict__ wvarg,
        const float* __restrict__ wqs, const float* __restrict__ wks,
        const float* __restrict__ wvs, int T, int D) {
    extern __shared__ float sw[];
    const int tid = threadIdx.x;
    for (int k = tid; k < 2 * D; k += blockDim.x) {
        sw[k]         = wqp[k];
        sw[2 * D + k] = wkp[k];
        sw[4 * D + k] = wqs[k];
        sw[6 * D + k] = wks[k];
    }
    for (int k = tid; k < D; k += blockDim.x) {
        sw[8 * D + k]  = wvop[k];
        sw[9 * D + k]  = wvarg[k];
        sw[10 * D + k] = wvs[k];
    }
    __syncthreads();
    int i = blockIdx.x * blockDim.x + tid;
    if (i >= T) return;
    const float* e = emb + (size_t)i * D;
    float a[11];
#pragma unroll
    for (int c = 0; c < 11; c++) a[c] = 0.f;
    for (int d = 0; d < D; d++) {
        float ev = e[d];
#pragma unroll
        for (int c = 0; c < 11; c++) a[c] = fmaf(ev, sw[c * D + d], a[c]);
    }
    g_QQ[i] = make_ulonglong2(packf2(a[0], a[4]), packf2(a[1], a[5]));
    g_KK[i] = make_ulonglong2(packf2(a[2], a[6]), packf2(a[3], a[7]));
    unsigned bp = qbins(a[0], a[1], a[4], a[5]);
    g_binPS[i] = bp;
    g_Vop[i] = a[8]; g_Varg[i] = a[9]; g_Vstk[i] = a[10];
    push_query(i, bp);
}

__global__ __launch_bounds__(BTH) void build_query_kernel(float* __restrict__ out, int T) {
    extern __shared__ ulonglong2 sKK2[];
    __shared__ int scandP[CAP], scandS[CAP];
    __shared__ float sVop[CAP], sVarg[CAP], sVstk[CAP];
    __shared__ int scnt[2];
    __shared__ float sred[4][NWRP];
    __shared__ float sth[2];

    const int b = blockIdx.x;
    const int tid = threadIdx.x, lane = tid & 31, w = tid >> 5;
    const float DLT = TWO_PI_F / NB;
    const float thb = -PI_F + (b + 0.5f) * DLT;
    const float ux = cosf(thb), uy = sinf(thb);
    const unsigned long long ua = packf2(ux, ux), ub = packf2(uy, uy);

    float v[4] = {-FLT_MAX, -FLT_MAX, 0.f, 0.f};
#pragma unroll 4
    for (int j = tid; j < T; j += BTH) {
        ulonglong2 kk = g_KK[j];
        sKK2[j] = kk;
        unsigned long long s  = fma2(ua, kk.x, mul2(ub, kk.y));
        unsigned long long n2 = fma2(kk.x, kk.x, mul2(kk.y, kk.y));
        v[0] = fmaxf(v[0], lo32(s));  v[1] = fmaxf(v[1], hi32(s));
        v[2] = fmaxf(v[2], lo32(n2)); v[3] = fmaxf(v[3], hi32(n2));
    }
#pragma unroll
    for (int c = 0; c < 4; c++) {
#pragma unroll
        for (int off = 16; off; off >>= 1)
            v[c] = fmaxf(v[c], __shfl_xor_sync(0xffffffffu, v[c], off));
        if (lane == 0) sred[c][w] = v[c];
    }
    if (tid < 2) scnt[tid] = 0;
    __syncthreads();
    if (tid < 2) {
        float M = sred[tid][0], N2 = sred[2 + tid][0];
#pragma unroll
        for (int k = 1; k < NWRP; k++) {
            M = fmaxf(M, sred[tid][k]);
            N2 = fmaxf(N2, sred[2 + tid][k]);
        }
        sth[tid] = M - 1.25f * sqrtf(N2) * DLT;
    }
    __syncthreads();
    const float tP = sth[0], tS = sth[1];

#pragma unroll 4
    for (int j = tid; j < T; j += BTH) {
        ulonglong2 kk = sKK2[j];
        unsigned long long s = fma2(ua, kk.x, mul2(ub, kk.y));
        if (lo32(s) >= tP) { int p = atomicAdd(&scnt[0], 1); if (p < CAP) scandP[p] = j; }
        if (hi32(s) >= tS) { int p = atomicAdd(&scnt[1], 1); if (p < CAP) scandS[p] = j; }
    }
    __syncthreads();
    const int nP = min(scnt[0], CAP), nS = min(scnt[1], CAP);
    for (int t = tid; t < nP; t += BTH) {
        int c = scandP[t];
        sVop[t] = g_Vop[c]; sVarg[t] = g_Varg[c];
    }
    for (int t = tid; t < nS; t += BTH) sVstk[t] = g_Vstk[scandS[t]];
    __syncthreads();

    const int totP = g_qcnt[b], totS = g_qcnt[NB + b];
    const int nqP = min(totP, CAPQ), nqS = min(totS, CAPQ);

    for (int t = tid; t < nqP; t += BTH) {
        const int i = g_qlistP[b * CAPQ + t];
        ulonglong2 q = g_QQ[i];
        const float qx = lo32(q.x), qy = lo32(q.y);
        float best = -FLT_MAX; int bi = 0x7fffffff, bt = 0;
        for (int c = 0; c < nP; c++) {
            int kj = scandP[c];
            ulonglong2 k2 = sKK2[kj];
            float sc = fmaf(qx, lo32(k2.x), __fmul_rn(qy, lo32(k2.y)));
            if (sc > best || (sc == best && kj < bi)) { best = sc; bi = kj; bt = c; }
        }
        out[i]     = sVop[bt];
        out[T + i] = sVarg[bt];
    }
    for (int t = tid; t < nqS; t += BTH) {
        const int i = g_qlistS[b * CAPQ + t];
        ulonglong2 q = g_QQ[i];
        const float qx = hi32(q.x), qy = hi32(q.y);
        float best = -FLT_MAX; int bi = 0x7fffffff, bt = 0;
        for (int c = 0; c < nS; c++) {
            int kj = scandS[c];
            ulonglong2 k2 = sKK2[kj];
            float sc = fmaf(qx, hi32(k2.x), __fmul_rn(qy, hi32(k2.y)));
            if (sc > best || (sc == best && kj < bi)) { best = sc; bi = kj; bt = c; }
        }
        out[2 * T + i] = sVstk[bt];
    }

    if (totP > CAPQ) {
        for (int j = tid; j < T; j += BTH) {
            if ((g_binPS[j] & 0xffffu) == (unsigned)b) {
                ulonglong2 q = g_QQ[j];
                const float qx = lo32(q.x), qy = lo32(q.y);
                float best = -FLT_MAX; int bi = 0x7fffffff, bt = 0;
                for (int c = 0; c < nP; c++) {
                    int kj = scandP[c];
                    ulonglong2 k2 = sKK2[kj];
                    float sc = fmaf(qx, lo32(k2.x), __fmul_rn(qy, lo32(k2.y)));
                    if (sc > best || (sc == best && kj < bi)) { best = sc; bi = kj; bt = c; }
                }
                out[j]     = sVop[bt];
                out[T + j] = sVarg[bt];
            }
        }
    }
    if (totS > CAPQ) {
        for (int j = tid; j < T; j += BTH) {
            if ((g_binPS[j] >> 16) == (unsigned)b) {
                ulonglong2 q = g_QQ[j];
                const float qx = hi32(q.x), qy = hi32(q.y);
                float best = -FLT_MAX; int bi = 0x7fffffff, bt = 0;
                for (int c = 0; c < nS; c++) {
                    int kj = scandS[c];
                    ulonglong2 k2 = sKK2[kj];
                    float sc = fmaf(qx, hi32(k2.x), __fmul_rn(qy, hi32(k2.y)));
                    if (sc > best || (sc == best && kj < bi)) { best = sc; bi = kj; bt = c; }
                }
                out[2 * T + j] = sVstk[bt];
            }
        }
    }

    __syncthreads();
    if (tid == 0) { g_qcnt[b] = 0; g_qcnt[NB + b] = 0; }   // self-reset
}

extern "C" void kernel_launch(void* const* d_in, const int* in_sizes, int n_in,
                              void* d_out, int out_size) {
    const float* emb   = (const float*)d_in[0];
    const float* wqp   = (const float*)d_in[1];
    const float* wkp   = (const float*)d_in[2];
    const float* wvop  = (const float*)d_in[3];
    const float* wvarg = (const float*)d_in[4];
    const float* wqs   = (const float*)d_in[5];
    const float* wks   = (const float*)d_in[6];
    const float* wvs   = (const float*)d_in[7];
    float* out = (float*)d_out;

    const int D = in_sizes[1] / 2;   // WQ_prog is (2, D)
    const int T = in_sizes[0] / D;   // embeddings is (T, D)

    const size_t KSMEM = (size_t)MAXT * sizeof(ulonglong2);   // 128 KB

    if (D == PD && T == MAXT) {
        cudaFuncSetAttribute(mega_kernel,
                             cudaFuncAttributeMaxDynamicSharedMemorySize, KSMEM);
        mega_kernel<<<NB, BTH, KSMEM>>>(emb, wqp, wkp, wvop, wvarg, wqs, wks, wvs, out);
    } else {
        const int pb = (T + 255) / 256;
        proj_generic_kernel<<<pb, 256, (size_t)(11 * D) * sizeof(float)>>>(
            emb, wqp, wkp, wvop, wvarg, wqs, wks, wvs, T, D);
        cudaFuncSetAttribute(build_query_kernel,
                             cudaFuncAttributeMaxDynamicSharedMemorySize, KSMEM);
        build_query_kernel<<<NB, BTH, KSMEM>>>(out, T);
    }
}